// round 14
// baseline (speedup 1.0000x reference)
#include <cuda_runtime.h>
#include <cstdint>
#include <cfloat>

// Problem constants
#define Bz 16
#define Cz 64
#define Nz 4096
#define Qz 8
#define Kz 8192
#define BNz (Bz*Nz)          // 65536 points
#define TM 128               // points per block
#define TN 128               // codes per tile
#define NTILES (Kz/TN)       // 64
#define NBLK (BNz/TM)        // 512 blocks per quantizer step

// Scratch (no allocations allowed)
__device__ float g_res[BNz*Cz];          // residual, [point][c], 16 MB
__device__ float g_cbT[Qz*Cz*Kz];        // codebook transposed [q][c][k], 16 MB
__device__ float g_cbsq[Qz*Kz];          // |cb|^2 per code
__device__ float g_losspart[Qz*NBLK];    // per-block loss partials

static __device__ __forceinline__ void cp_async16(uint32_t s, const void* g) {
    asm volatile("cp.async.cg.shared.global [%0], [%1], 16;\n" :: "r"(s), "l"(g));
}

// ---------------------------------------------------------------------------
__global__ void cbsq_kernel(const float* __restrict__ cb) {
    int i = blockIdx.x * blockDim.x + threadIdx.x;   // q*K + k
    if (i >= Qz*Kz) return;
    const float4* row = (const float4*)(cb + (size_t)i * Cz);
    float s = 0.f;
#pragma unroll
    for (int j = 0; j < Cz/4; ++j) {
        float4 v = row[j];
        s += v.x*v.x + v.y*v.y + v.z*v.z + v.w*v.w;
    }
    g_cbsq[i] = s;
}

// codebook transpose: [q][k][c] -> [q][c][k]   (32x32 smem tiles)
__global__ void transpose_cb_kernel(const float* __restrict__ cb) {
    __shared__ float sm[32][33];
    const int q  = blockIdx.z;
    const int kt = blockIdx.x * 32;
    const int ct = blockIdx.y * 32;
    const float* src = cb + (size_t)q * Kz * Cz;
    float* dst = g_cbT + (size_t)q * Cz * Kz;
#pragma unroll
    for (int j = 0; j < 4; ++j) {
        int k = kt + threadIdx.y + j * 8;
        sm[threadIdx.y + j * 8][threadIdx.x] = src[(size_t)k * Cz + ct + threadIdx.x];
    }
    __syncthreads();
#pragma unroll
    for (int j = 0; j < 4; ++j) {
        int c = ct + threadIdx.y + j * 8;
        dst[(size_t)c * Kz + kt + threadIdx.x] = sm[threadIdx.x][threadIdx.y + j * 8];
    }
}

// residual := x transposed to point-major [B*N, C]
__global__ void init_kernel(const float* __restrict__ x) {
    int i = blockIdx.x * blockDim.x + threadIdx.x;   // p*C + c
    if (i >= BNz*Cz) return;
    int p = i >> 6, c = i & 63;
    int b = p >> 12, n = p & (Nz - 1);
    g_res[i] = x[((size_t)b * Cz + c) * Nz + n];
}

// ---------------------------------------------------------------------------
// One RVQ step. 8 points x 16 codes register tile (acc = 128 fp32 regs),
// TM=128 / TN=128, block=128. Code tiles double-buffered via cp.async with a
// single __syncthreads per tile (wait -> sync -> prefetch-next -> compute).
// 2 CTAs/SM (96 KB smem, up to 256 regs/thread).
__global__ void __launch_bounds__(128, 2) rvq_step(
    const float* __restrict__ cb,      // this quantizer's codebook [K][C] (epilogue)
    const float* __restrict__ cbT,     // this quantizer's codebook [C][K]
    int q,
    float* __restrict__ out_idx)       // may be null
{
    __shared__ float s_resT[Cz][TM];   // residual tile, transposed  (32 KB)
    __shared__ float s_cb[2][Cz][TN];  // code tiles, c-major        (2 x 32 KB)

    const int tid = threadIdx.x;
    const int tx  = tid & 7;           // code-group  (8)  -> codes jg*32 + tx*4 + e
    const int ty  = tid >> 3;          // point-group (16) -> points ty*8 + i
    const int pbase = blockIdx.x * TM;

    const float* cbsq = g_cbsq + (size_t)q * Kz;

    // ---- load residual tile (transpose into smem). 1 thread per point row.
    {
        const float4* src = (const float4*)(g_res + ((size_t)(pbase + tid)) * Cz);
#pragma unroll
        for (int j = 0; j < 16; ++j) {
            float4 v = src[j];
            int c0 = j * 4;
            s_resT[c0+0][tid] = v.x; s_resT[c0+1][tid] = v.y;
            s_resT[c0+2][tid] = v.z; s_resT[c0+3][tid] = v.w;
        }
    }

    uint32_t cbsm0 = (uint32_t)__cvta_generic_to_shared(&s_cb[0][0][0]);
    uint32_t cbsm1 = (uint32_t)__cvta_generic_to_shared(&s_cb[1][0][0]);

    // prefetch tile 0: 2048 float4; 16 cp.async per thread
#define PREFETCH_TILE(TT, DSTB) do {                                            \
        const float4* _src = (const float4*)(cbT + (TT) * TN);                  \
        _Pragma("unroll")                                                       \
        for (int _i = 0; _i < 16; ++_i) {                                       \
            int _f = _i * 128 + tid;                                            \
            int _row = _f >> 5, _col4 = _f & 31;                                \
            cp_async16((DSTB) + _f * 16, _src + (size_t)_row * (Kz/4) + _col4); \
        }                                                                       \
        asm volatile("cp.async.commit_group;\n");                               \
    } while (0)

    PREFETCH_TILE(0, cbsm0);

    float bestd[8];
    int   bestk[8];
#pragma unroll
    for (int i = 0; i < 8; ++i) { bestd[i] = FLT_MAX; bestk[i] = 0; }

    for (int t = 0; t < NTILES; ++t) {
        const int kbase = t * TN;
        asm volatile("cp.async.wait_group 0;\n");   // tile t resident
        __syncthreads();                            // everyone past compute(t-1)

        if (t + 1 < NTILES)                         // overlaps with compute(t)
            PREFETCH_TILE(t + 1, ((t + 1) & 1) ? cbsm1 : cbsm0);

        // ---- 8 points x 16 codes register tile over c = 0..63
        const float (*cbt)[TN] = s_cb[t & 1];
        float acc[8][16];
#pragma unroll
        for (int i = 0; i < 8; ++i)
#pragma unroll
            for (int j = 0; j < 16; ++j) acc[i][j] = 0.f;

#pragma unroll 2
        for (int c = 0; c < Cz; ++c) {
            float4 r0 = *(const float4*)&s_resT[c][ty * 8];
            float4 r1 = *(const float4*)&s_resT[c][ty * 8 + 4];
            float4 b0 = *(const float4*)&cbt[c][tx * 4];
            float4 b1 = *(const float4*)&cbt[c][32 + tx * 4];
            float4 b2 = *(const float4*)&cbt[c][64 + tx * 4];
            float4 b3 = *(const float4*)&cbt[c][96 + tx * 4];
            float rv[8] = {r0.x, r0.y, r0.z, r0.w, r1.x, r1.y, r1.z, r1.w};
            float cv[16] = {b0.x, b0.y, b0.z, b0.w, b1.x, b1.y, b1.z, b1.w,
                            b2.x, b2.y, b2.z, b2.w, b3.x, b3.y, b3.z, b3.w};
#pragma unroll
            for (int i = 0; i < 8; ++i)
#pragma unroll
                for (int j = 0; j < 16; ++j)
                    acc[i][j] = fmaf(rv[i], cv[j], acc[i][j]);
        }

        // ---- dist = |cb|^2 - 2*dot ; running argmin.
        // k strictly increases within a thread over (t, jg, e): strict '<'
        // keeps the lowest tied index automatically.
#pragma unroll
        for (int jg = 0; jg < 4; ++jg) {
            float4 v = *(const float4*)&cbsq[kbase + jg * 32 + tx * 4];
            float cbs[4] = {v.x, v.y, v.z, v.w};
#pragma unroll
            for (int i = 0; i < 8; ++i) {
#pragma unroll
                for (int e = 0; e < 4; ++e) {
                    float d = fmaf(-2.f, acc[i][jg*4+e], cbs[e]);
                    int   k = kbase + jg * 32 + tx * 4 + e;
                    if (d < bestd[i]) { bestd[i] = d; bestk[i] = k; }
                }
            }
        }
    }

    // ---- reduce across the 8 tx-threads (xor butterfly stays in ty-half)
#pragma unroll
    for (int off = 1; off < 8; off <<= 1) {
#pragma unroll
        for (int i = 0; i < 8; ++i) {
            float od = __shfl_xor_sync(0xffffffffu, bestd[i], off);
            int   ok = __shfl_xor_sync(0xffffffffu, bestk[i], off);
            if (od < bestd[i] || (od == bestd[i] && ok < bestk[i])) {
                bestd[i] = od; bestk[i] = ok;
            }
        }
    }

    __syncthreads();                       // tile reads done; reuse s_cb space
    int*   s_k = (int*)&s_cb[0][0][0];     // 128 ints
    float* s_l = &s_cb[0][2][0];           // 4 floats for warp partials
    if (tx == 0) {
#pragma unroll
        for (int i = 0; i < 8; ++i) s_k[ty * 8 + i] = bestk[i];
    }
    __syncthreads();

    // ---- fused residual update + loss partial (TM*Cz = 8192 elems)
    float lsum = 0.f;
#pragma unroll
    for (int e0 = 0; e0 < TM * Cz; e0 += 128) {
        int e = e0 + tid;
        int p = e >> 6, c = e & 63;
        float code = cb[(size_t)s_k[p] * Cz + c];
        float rnew = g_res[(size_t)pbase * Cz + e] - code;
        g_res[(size_t)pbase * Cz + e] = rnew;
        lsum += rnew * rnew;
    }
#pragma unroll
    for (int off = 16; off > 0; off >>= 1)
        lsum += __shfl_xor_sync(0xffffffffu, lsum, off);
    if ((tid & 31) == 0) s_l[tid >> 5] = lsum;
    __syncthreads();
    if (tid == 0)
        g_losspart[q * NBLK + blockIdx.x] = s_l[0] + s_l[1] + s_l[2] + s_l[3];

    if (out_idx != nullptr)
        out_idx[(size_t)(pbase + tid) * Qz + q] = (float)s_k[tid];
#undef PREFETCH_TILE
}

// ---------------------------------------------------------------------------
// quantized = x - final residual, back in [B, C, N] layout
__global__ void final_kernel(const float* __restrict__ x, float* __restrict__ out) {
    int i = blockIdx.x * blockDim.x + threadIdx.x;
    if (i >= Bz*Cz*Nz) return;
    int n = i & (Nz - 1);
    int c = (i >> 12) & 63;
    int b = i >> 18;
    int p = (b << 12) | n;
    out[i] = x[i] - g_res[(size_t)p * Cz + c];
}

// mean loss: deterministic single-block reduction over Q*NBLK partials
__global__ void loss_kernel(float* __restrict__ out_loss) {
    __shared__ float sm[256];
    float s = 0.f;
    for (int i = threadIdx.x; i < Qz * NBLK; i += 256) s += g_losspart[i];
    sm[threadIdx.x] = s;
    __syncthreads();
    for (int w = 128; w > 0; w >>= 1) {
        if (threadIdx.x < w) sm[threadIdx.x] += sm[threadIdx.x + w];
        __syncthreads();
    }
    if (threadIdx.x == 0)
        *out_loss = sm[0] / ((float)Qz * (float)BNz * (float)Cz);
}

// ---------------------------------------------------------------------------
extern "C" void kernel_launch(void* const* d_in, const int* in_sizes, int n_in,
                              void* d_out, int out_size) {
    const float* x  = (const float*)d_in[0];   // [B, C, N]
    const float* cb = (const float*)d_in[1];   // [Q, K, C]
    float* out = (float*)d_out;

    const int OUTQ = Bz * Cz * Nz;                       // 4,194,304
    const bool full = out_size >= OUTQ + BNz * Qz + 1;   // quantized + indices + loss
    float* idx_out  = full ? out + OUTQ : nullptr;
    float* loss_out = full ? out + OUTQ + BNz * Qz : nullptr;

    cbsq_kernel<<<(Qz*Kz + 255) / 256, 256>>>(cb);
    {
        dim3 g(Kz/32, Cz/32, Qz), b(32, 8);
        transpose_cb_kernel<<<g, b>>>(cb);
    }
    init_kernel<<<(BNz*Cz + 255) / 256, 256>>>(x);

    float* cbT_base;
    cudaGetSymbolAddress((void**)&cbT_base, g_cbT);
    for (int q = 0; q < Qz; ++q)
        rvq_step<<<NBLK, 128>>>(cb + (size_t)q * Kz * Cz,
                                cbT_base + (size_t)q * Cz * Kz, q, idx_out);
    final_kernel<<<(OUTQ + 255) / 256, 256>>>(x, out);
    if (full) loss_kernel<<<1, 256>>>(loss_out);
}

// round 16
// speedup vs baseline: 1.8939x; 1.8939x over previous
#include <cuda_runtime.h>
#include <cstdint>
#include <cfloat>

// Problem constants
#define Bz 16
#define Cz 64
#define Nz 4096
#define Qz 8
#define Kz 8192
#define BNz (Bz*Nz)          // 65536 points
#define TM 64                // points per CTA
#define TN 128               // codes per tile
#define KSPLIT 2
#define KHALF (Kz/KSPLIT)    // 4096
#define NTILES (KHALF/TN)    // 32
#define NPB (BNz/TM)         // 1024 point-blocks
#define NBLK NPB

// Scratch (no allocations allowed)
__device__ float              g_res[BNz*Cz];       // residual, [point][c], 16 MB
__device__ float              g_cbT[Qz*Cz*Kz];     // codebook transposed [q][c][k], 16 MB
__device__ float              g_cbsq[Qz*Kz];       // |cb|^2 per code
__device__ unsigned long long g_part[KSPLIT*BNz];  // per-half packed (enc(d),k), 1 MB
__device__ float              g_losspart[Qz*NBLK]; // per-block loss partials

// float -> order-preserving uint32 (no NaNs here)
static __device__ __forceinline__ uint32_t encf(float d) {
    uint32_t u = __float_as_uint(d);
    return (u & 0x80000000u) ? ~u : (u | 0x80000000u);
}

// ---------------------------------------------------------------------------
__global__ void cbsq_kernel(const float* __restrict__ cb) {
    int i = blockIdx.x * blockDim.x + threadIdx.x;   // q*K + k
    if (i >= Qz*Kz) return;
    const float4* row = (const float4*)(cb + (size_t)i * Cz);
    float s = 0.f;
#pragma unroll
    for (int j = 0; j < Cz/4; ++j) {
        float4 v = row[j];
        s += v.x*v.x + v.y*v.y + v.z*v.z + v.w*v.w;
    }
    g_cbsq[i] = s;
}

// codebook transpose: [q][k][c] -> [q][c][k]   (32x32 smem tiles)
__global__ void transpose_cb_kernel(const float* __restrict__ cb) {
    __shared__ float sm[32][33];
    const int q  = blockIdx.z;
    const int kt = blockIdx.x * 32;
    const int ct = blockIdx.y * 32;
    const float* src = cb + (size_t)q * Kz * Cz;
    float* dst = g_cbT + (size_t)q * Cz * Kz;
#pragma unroll
    for (int j = 0; j < 4; ++j) {
        int k = kt + threadIdx.y + j * 8;
        sm[threadIdx.y + j * 8][threadIdx.x] = src[(size_t)k * Cz + ct + threadIdx.x];
    }
    __syncthreads();
#pragma unroll
    for (int j = 0; j < 4; ++j) {
        int c = ct + threadIdx.y + j * 8;
        dst[(size_t)c * Kz + kt + threadIdx.x] = sm[threadIdx.x][threadIdx.y + j * 8];
    }
}

// residual := x transposed to point-major [B*N, C]
__global__ void init_kernel(const float* __restrict__ x) {
    int i = blockIdx.x * blockDim.x + threadIdx.x;   // p*C + c
    if (i >= BNz*Cz) return;
    int p = i >> 6, c = i & 63;
    int b = p >> 12, n = p & (Nz - 1);
    g_res[i] = x[((size_t)b * Cz + c) * Nz + n];
}

// ---------------------------------------------------------------------------
// Distance + argmin over one K-half for 64 points. 8 pts x 8 codes register
// tile (round-9 inner loop), TN=128 tiles from the pre-transposed codebook.
// 48 KB smem -> 3 CTAs/SM, grid 2048 -> 4.6 waves (small tail).
__global__ void __launch_bounds__(128, 3) rvq_dist(
    const float* __restrict__ cbT,     // this quantizer's codebook [C][K]
    const float* __restrict__ cbsq,    // this quantizer's |cb|^2 [K]
    unsigned long long* __restrict__ part)
{
    __shared__ float s_resT[Cz][TM];   // residual tile, transposed  (16 KB)
    __shared__ float s_cb[Cz][TN];     // code tile, c-major         (32 KB)
    __shared__ float s_d[TM];
    __shared__ int   s_i[TM];

    const int tid  = threadIdx.x;
    const int tx   = tid & 15;         // code-group  (16) -> codes jg*64 + tx*4 + e
    const int ty   = tid >> 4;         // point-group (8)  -> points ty*8 + i
    const int pblk = blockIdx.x >> 1;
    const int half = blockIdx.x & 1;
    const int pbase = pblk * TM;
    const int kofs  = half * KHALF;

    // ---- load residual tile (transpose into smem). 2 threads per point row.
    {
        int p  = tid & 63;
        int ch = tid >> 6;             // 0/1 -> covers c 0..31 / 32..63
        const float4* src = (const float4*)(g_res + ((size_t)(pbase + p)) * Cz + ch * 32);
#pragma unroll
        for (int i = 0; i < 8; ++i) {
            float4 v = src[i];
            int c0 = ch * 32 + i * 4;
            s_resT[c0+0][p] = v.x; s_resT[c0+1][p] = v.y;
            s_resT[c0+2][p] = v.z; s_resT[c0+3][p] = v.w;
        }
    }

    float bestd[8];
    int   bestk[8];
#pragma unroll
    for (int i = 0; i < 8; ++i) { bestd[i] = FLT_MAX; bestk[i] = 0; }

    for (int t = 0; t < NTILES; ++t) {
        const int kbase = kofs + t * TN;
        __syncthreads();   // previous tile fully consumed before overwrite
        // ---- fill code tile (vectorized, from transposed codebook)
        // 64 c-rows x TN=128 floats = 2048 float4 -> 16 iters x 128 threads
        {
            const float4* src = (const float4*)(cbT + kbase);   // row stride Kz/4
            float4* dst = (float4*)&s_cb[0][0];
#pragma unroll
            for (int i = 0; i < 16; ++i) {
                int f = i * 128 + tid;         // 2048 float4 per tile
                int row = f >> 5, col4 = f & 31;  // 32 float4 per c-row
                dst[f] = src[(size_t)row * (Kz/4) + col4];
            }
        }
        __syncthreads();

        // ---- 8 points x 8 codes register tile over c = 0..63
        float acc[8][8];
#pragma unroll
        for (int i = 0; i < 8; ++i)
#pragma unroll
            for (int j = 0; j < 8; ++j) acc[i][j] = 0.f;

#pragma unroll 2
        for (int c = 0; c < Cz; ++c) {
            float4 r0 = *(const float4*)&s_resT[c][ty * 8];
            float4 r1 = *(const float4*)&s_resT[c][ty * 8 + 4];
            float4 b0 = *(const float4*)&s_cb[c][tx * 4];
            float4 b1 = *(const float4*)&s_cb[c][64 + tx * 4];
            float rv[8] = {r0.x, r0.y, r0.z, r0.w, r1.x, r1.y, r1.z, r1.w};
            float cv[8] = {b0.x, b0.y, b0.z, b0.w, b1.x, b1.y, b1.z, b1.w};
#pragma unroll
            for (int i = 0; i < 8; ++i)
#pragma unroll
                for (int j = 0; j < 8; ++j)
                    acc[i][j] = fmaf(rv[i], cv[j], acc[i][j]);
        }

        // ---- dist = |cb|^2 - 2*dot ; running argmin.
        // k strictly increases within a thread: strict '<' keeps lowest tie.
#pragma unroll
        for (int jg = 0; jg < 2; ++jg) {
            float4 v = *(const float4*)&cbsq[kbase + jg * 64 + tx * 4];
            float cbs[4] = {v.x, v.y, v.z, v.w};
#pragma unroll
            for (int i = 0; i < 8; ++i) {
#pragma unroll
                for (int e = 0; e < 4; ++e) {
                    float d = fmaf(-2.f, acc[i][jg*4+e], cbs[e]);
                    int   k = kbase + jg * 64 + tx * 4 + e;
                    if (d < bestd[i]) { bestd[i] = d; bestk[i] = k; }
                }
            }
        }
    }

    // ---- reduce across the 16 tx-threads (xor butterfly stays in ty-half)
#pragma unroll
    for (int off = 1; off < 16; off <<= 1) {
#pragma unroll
        for (int i = 0; i < 8; ++i) {
            float od = __shfl_xor_sync(0xffffffffu, bestd[i], off);
            int   ok = __shfl_xor_sync(0xffffffffu, bestk[i], off);
            if (od < bestd[i] || (od == bestd[i] && ok < bestk[i])) {
                bestd[i] = od; bestk[i] = ok;
            }
        }
    }
    if (tx == 0) {
#pragma unroll
        for (int i = 0; i < 8; ++i) {
            s_d[ty * 8 + i] = bestd[i];
            s_i[ty * 8 + i] = bestk[i];
        }
    }
    __syncthreads();

    if (tid < TM) {
        unsigned long long pk =
            ((unsigned long long)encf(s_d[tid]) << 32) | (uint32_t)s_i[tid];
        part[(size_t)half * BNz + pbase + tid] = pk;
    }
}

// ---------------------------------------------------------------------------
// Merge K-halves (exact, deterministic), residual update, loss, index write.
__global__ void __launch_bounds__(128) rvq_update(
    const float* __restrict__ cb,      // this quantizer's codebook [K][C]
    int q,
    float* __restrict__ out_idx)       // may be null
{
    __shared__ int   s_k[TM];
    __shared__ float s_l[4];

    const int tid = threadIdx.x;
    const int pbase = blockIdx.x * TM;

    if (tid < TM) {
        unsigned long long a = g_part[pbase + tid];
        unsigned long long b = g_part[BNz + pbase + tid];
        unsigned long long m = (a < b) ? a : b;   // lower d, tie -> lower k
        s_k[tid] = (int)(uint32_t)m;
    }
    __syncthreads();

    float lsum = 0.f;
#pragma unroll
    for (int e0 = 0; e0 < TM * Cz; e0 += 128) {
        int e = e0 + tid;
        int p = e >> 6, c = e & 63;
        float code = cb[(size_t)s_k[p] * Cz + c];
        float rnew = g_res[(size_t)pbase * Cz + e] - code;
        g_res[(size_t)pbase * Cz + e] = rnew;
        lsum += rnew * rnew;
    }
#pragma unroll
    for (int off = 16; off > 0; off >>= 1)
        lsum += __shfl_xor_sync(0xffffffffu, lsum, off);
    if ((tid & 31) == 0) s_l[tid >> 5] = lsum;
    __syncthreads();
    if (tid == 0)
        g_losspart[q * NBLK + blockIdx.x] = s_l[0] + s_l[1] + s_l[2] + s_l[3];

    if (out_idx != nullptr && tid < TM)
        out_idx[(size_t)(pbase + tid) * Qz + q] = (float)s_k[tid];
}

// ---------------------------------------------------------------------------
// quantized = x - final residual, back in [B, C, N] layout
__global__ void final_kernel(const float* __restrict__ x, float* __restrict__ out) {
    int i = blockIdx.x * blockDim.x + threadIdx.x;
    if (i >= Bz*Cz*Nz) return;
    int n = i & (Nz - 1);
    int c = (i >> 12) & 63;
    int b = i >> 18;
    int p = (b << 12) | n;
    out[i] = x[i] - g_res[(size_t)p * Cz + c];
}

// mean loss: deterministic single-block reduction over Q*NBLK partials
__global__ void loss_kernel(float* __restrict__ out_loss) {
    __shared__ float sm[256];
    float s = 0.f;
    for (int i = threadIdx.x; i < Qz * NBLK; i += 256) s += g_losspart[i];
    sm[threadIdx.x] = s;
    __syncthreads();
    for (int w = 128; w > 0; w >>= 1) {
        if (threadIdx.x < w) sm[threadIdx.x] += sm[threadIdx.x + w];
        __syncthreads();
    }
    if (threadIdx.x == 0)
        *out_loss = sm[0] / ((float)Qz * (float)BNz * (float)Cz);
}

// ---------------------------------------------------------------------------
extern "C" void kernel_launch(void* const* d_in, const int* in_sizes, int n_in,
                              void* d_out, int out_size) {
    const float* x  = (const float*)d_in[0];   // [B, C, N]
    const float* cb = (const float*)d_in[1];   // [Q, K, C]
    float* out = (float*)d_out;

    const int OUTQ = Bz * Cz * Nz;                       // 4,194,304
    const bool full = out_size >= OUTQ + BNz * Qz + 1;   // quantized + indices + loss
    float* idx_out  = full ? out + OUTQ : nullptr;
    float* loss_out = full ? out + OUTQ + BNz * Qz : nullptr;

    cbsq_kernel<<<(Qz*Kz + 255) / 256, 256>>>(cb);
    {
        dim3 g(Kz/32, Cz/32, Qz), b(32, 8);
        transpose_cb_kernel<<<g, b>>>(cb);
    }
    init_kernel<<<(BNz*Cz + 255) / 256, 256>>>(x);

    float* cbT_base;
    float* cbsq_base;
    cudaGetSymbolAddress((void**)&cbT_base, g_cbT);
    cudaGetSymbolAddress((void**)&cbsq_base, g_cbsq);
    unsigned long long* part_base;
    cudaGetSymbolAddress((void**)&part_base, g_part);

    for (int q = 0; q < Qz; ++q) {
        rvq_dist<<<NPB * KSPLIT, 128>>>(cbT_base + (size_t)q * Cz * Kz,
                                        cbsq_base + (size_t)q * Kz, part_base);
        rvq_update<<<NPB, 128>>>(cb + (size_t)q * Kz * Cz, q, idx_out);
    }
    final_kernel<<<(OUTQ + 255) / 256, 256>>>(x, out);
    if (full) loss_kernel<<<1, 256>>>(loss_out);
}